// round 12
// baseline (speedup 1.0000x reference)
#include <cuda_runtime.h>

// SmallRNN: h_t = tanh(x_t * w_ih^T + b_ih + h_{t-1} * w_hh^T + b_hh), out = h_T @ fc_w^T + fc_b
// Shapes: x [B=4096, T=2048, I=1], w_ih [8,1], w_hh [8,8], b_* [8], fc_w [1,8], fc_b [1]
//
// R10: 8 lanes per element (1 tanh per lane, MUFU-minimal), smem exchange
// (asm STS -> 2x LDS.128, memory-clobbered — proven R6). Each group carries
// TWO elements PHASE-OFFSET: while element A's LDS is in flight, the warp
// computes element B's tree+tanh (and vice versa), hiding the ~35-cycle
// LDS visibility latency that dominates R6's chain.
// tanh.approx for first T-64 steps, exact ex2+rcp tail (recurrence contracts).

#define TBLOCK 256
#define EXACT_TAIL 64

__device__ __forceinline__ float ex2f(float x) {
    float y; asm("ex2.approx.f32 %0, %1;" : "=f"(y) : "f"(x)); return y;
}
__device__ __forceinline__ float rcpf(float x) {
    float y; asm("rcp.approx.f32 %0, %1;" : "=f"(y) : "f"(x)); return y;
}
__device__ __forceinline__ float tanhf_approx(float x) {
    float y; asm("tanh.approx.f32 %0, %1;" : "=f"(y) : "f"(x)); return y;
}

template <bool EXACT>
__device__ __forceinline__ float act(float s) {
    if (EXACT) {
        const float c2 = 2.8853900817779268f; // 2*log2(e)
        float e = ex2f(c2 * s);
        float r = rcpf(e + 1.0f);
        return fmaf(-2.0f, r, 1.0f); // tanh(s) = 1 - 2*sigmoid(-2s)
    } else {
        return tanhf_approx(s);
    }
}

__device__ __forceinline__ float tree8(const float v[8], float xv,
                                       const float w[8], float Bj, float wih) {
    float a = fmaf(xv, wih, Bj);
    a = fmaf(v[0], w[0], a);
    float b  = v[1] * w[1];
    float cc = v[2] * w[2];
    float d  = v[3] * w[3];
    a  = fmaf(v[4], w[4], a);
    b  = fmaf(v[5], w[5], b);
    cc = fmaf(v[6], w[6], cc);
    d  = fmaf(v[7], w[7], d);
    return (a + b) + (cc + d);
}

#define STS1(addr, val) \
    asm volatile("st.shared.f32 [%0], %1;" :: "r"(addr), "f"(val) : "memory")
#define LDS8(v, addr) \
    do { \
        asm volatile("ld.shared.v4.f32 {%0,%1,%2,%3}, [%4];" \
                     : "=f"(v[0]), "=f"(v[1]), "=f"(v[2]), "=f"(v[3]) \
                     : "r"(addr) : "memory"); \
        asm volatile("ld.shared.v4.f32 {%0,%1,%2,%3}, [%4];" \
                     : "=f"(v[4]), "=f"(v[5]), "=f"(v[6]), "=f"(v[7]) \
                     : "r"((addr) + 16u) : "memory"); \
    } while (0)

// One time step for both elements, phase-offset: A's LDS flies during B's
// compute phase and vice versa.
template <bool EXACT>
__device__ __forceinline__ void step_pair(float vA[8], float vB[8],
                                          float xvA, float xvB,
                                          unsigned ownA, unsigned vecA,
                                          unsigned ownB, unsigned vecB,
                                          const float w[8], float Bj, float wih) {
    float sA = tree8(vA, xvA, w, Bj, wih);
    float hA = act<EXACT>(sA);
    STS1(ownA, hA);
    LDS8(vA, vecA);            // in flight during B's phase
    float sB = tree8(vB, xvB, w, Bj, wih);
    float hB = act<EXACT>(sB);
    STS1(ownB, hB);
    LDS8(vB, vecB);            // in flight during next iteration's A phase
}

__global__ void __launch_bounds__(TBLOCK)
SmallRNN_kernel(const float* __restrict__ x,
                const float* __restrict__ w_ih,
                const float* __restrict__ w_hh,
                const float* __restrict__ b_ih,
                const float* __restrict__ b_hh,
                const float* __restrict__ fc_w,
                const float* __restrict__ fc_b,
                float* __restrict__ out,
                int B, int T) {
    __shared__ float sh[2 * TBLOCK];

    int tx = threadIdx.x;
    int j = tx & 7;
    int g = tx >> 3;                    // 32 groups per block

    // Each block handles 64 elements: A = blk*64 + g, B = blk*64 + 32 + g
    int eA_raw = blockIdx.x * 64 + g;
    int eB_raw = eA_raw + 32;
    int eA = (eA_raw < B) ? eA_raw : (B - 1);
    int eB = (eB_raw < B) ? eB_raw : (B - 1);

    unsigned base = (unsigned)__cvta_generic_to_shared(sh);
    unsigned ownA = base + (unsigned)tx * 4u;
    unsigned vecA = base + (unsigned)(tx & ~7) * 4u;
    unsigned ownB = ownA + (unsigned)TBLOCK * 4u;
    unsigned vecB = vecA + (unsigned)TBLOCK * 4u;

    float w[8];
#pragma unroll
    for (int k = 0; k < 8; k++) w[k] = w_hh[j * 8 + k];
    float Bj  = b_ih[j] + b_hh[j];
    float wih = w_ih[j];

    const float* xpA = x + (size_t)eA * (size_t)T;
    const float* xpB = x + (size_t)eB * (size_t)T;

    // Prologue: publish h0 = 0 and prime both pipelines.
    float vA[8], vB[8];
    STS1(ownA, 0.0f);
    LDS8(vA, vecA);
    STS1(ownB, 0.0f);
    LDS8(vB, vecB);

    int Tmain = T - EXACT_TAIL;
    if (Tmain < 0) Tmain = 0;
    int Tm = Tmain & ~7;

    bool aligned = (((unsigned long long)xpA & 15ull) == 0ull) &&
                   (((unsigned long long)xpB & 15ull) == 0ull);
    if (aligned && Tm > 0) {
        float4 aA0 = *(const float4*)(xpA);
        float4 aA1 = *(const float4*)(xpA + 4);
        float4 aB0 = *(const float4*)(xpB);
        float4 aB1 = *(const float4*)(xpB + 4);
        for (int t = 0; t < Tm; t += 8) {
            float4 nA0, nA1, nB0, nB1;
            if (t + 8 < Tm) {
                nA0 = *(const float4*)(xpA + t + 8);
                nA1 = *(const float4*)(xpA + t + 12);
                nB0 = *(const float4*)(xpB + t + 8);
                nB1 = *(const float4*)(xpB + t + 12);
            } else {
                nA0 = make_float4(0.f, 0.f, 0.f, 0.f);
                nA1 = nA0; nB0 = nA0; nB1 = nA0;
            }
            step_pair<false>(vA, vB, aA0.x, aB0.x, ownA, vecA, ownB, vecB, w, Bj, wih);
            step_pair<false>(vA, vB, aA0.y, aB0.y, ownA, vecA, ownB, vecB, w, Bj, wih);
            step_pair<false>(vA, vB, aA0.z, aB0.z, ownA, vecA, ownB, vecB, w, Bj, wih);
            step_pair<false>(vA, vB, aA0.w, aB0.w, ownA, vecA, ownB, vecB, w, Bj, wih);
            step_pair<false>(vA, vB, aA1.x, aB1.x, ownA, vecA, ownB, vecB, w, Bj, wih);
            step_pair<false>(vA, vB, aA1.y, aB1.y, ownA, vecA, ownB, vecB, w, Bj, wih);
            step_pair<false>(vA, vB, aA1.z, aB1.z, ownA, vecA, ownB, vecB, w, Bj, wih);
            step_pair<false>(vA, vB, aA1.w, aB1.w, ownA, vecA, ownB, vecB, w, Bj, wih);
            aA0 = nA0; aA1 = nA1; aB0 = nB0; aB1 = nB1;
        }
    } else {
        Tm = 0;
    }
    for (int t = Tm; t < Tmain; t++) {
        step_pair<false>(vA, vB, xpA[t], xpB[t], ownA, vecA, ownB, vecB, w, Bj, wih);
    }
    for (int t = Tmain; t < T; t++) {
        step_pair<true>(vA, vB, xpA[t], xpB[t], ownA, vecA, ownB, vecB, w, Bj, wih);
    }

    // Final hidden states are in vA/vB (loaded after the last STS).
    // out[e] = sum_j h_j * fc_w[j] + fc_b — each lane already holds the full
    // h-vector, so compute the dot product redundantly (no reduction needed).
    float fb = fc_b[0];
    float accA = fb, accB = fb;
#pragma unroll
    for (int k = 0; k < 8; k++) {
        float fw = fc_w[k];
        accA = fmaf(vA[k], fw, accA);
        accB = fmaf(vB[k], fw, accB);
    }
    if (j == 0) {
        if (eA_raw < B) out[eA] = accA;
        if (eB_raw < B) out[eB] = accB;
    }
}

extern "C" void kernel_launch(void* const* d_in, const int* in_sizes, int n_in,
                              void* d_out, int out_size) {
    const float* x    = (const float*)d_in[0];
    const float* w_ih = (const float*)d_in[1];
    const float* w_hh = (const float*)d_in[2];
    const float* b_ih = (const float*)d_in[3];
    const float* b_hh = (const float*)d_in[4];
    const float* fc_w = (const float*)d_in[5];
    const float* fc_b = (const float*)d_in[6];
    float* out = (float*)d_out;

    int B = out_size;                 // O = 1
    int T = in_sizes[0] / B;          // I = 1
    int grid = (B + 63) / 64;         // 64 elements per 256-thread block
    SmallRNN_kernel<<<grid, TBLOCK>>>(x, w_ih, w_hh, b_ih, b_hh, fc_w, fc_b,
                                      out, B, T);
}

// round 13
// speedup vs baseline: 1.1064x; 1.1064x over previous
#include <cuda_runtime.h>

// SmallRNN: h_t = tanh(x_t * w_ih^T + b_ih + h_{t-1} * w_hh^T + b_hh), out = h_T @ fc_w^T + fc_b
// Shapes: x [B=4096, T=2048, I=1], w_ih [8,1], w_hh [8,8], b_* [8], fc_w [1,8], fc_b [1]
//
// R11 = R6 (90.6us) + micro-tweaks only:
//  - unroll 16 (halves loop/branch/prefetch-mux overhead per step)
//  - arrival-ordered tree: first LDS.128's values (v0-v3) on the deep path,
//    second LDS.128's (v4-v7, +4cyc later) at shallow depth
//  - own-h folded into base from the register (own weight zeroed in tree),
//    so base = f(x, bias, h_own) computes entirely in the LDS shadow
// Everything else identical to R6: 8 lanes/element, asm STS -> 2x LDS.128 with
// memory clobbers, tanh.approx main + exact ex2+rcp tail of 64 steps.

#define TBLOCK 256
#define EXACT_TAIL 64

__device__ __forceinline__ float ex2f(float x) {
    float y; asm("ex2.approx.f32 %0, %1;" : "=f"(y) : "f"(x)); return y;
}
__device__ __forceinline__ float rcpf(float x) {
    float y; asm("rcp.approx.f32 %0, %1;" : "=f"(y) : "f"(x)); return y;
}
__device__ __forceinline__ float tanhf_approx(float x) {
    float y; asm("tanh.approx.f32 %0, %1;" : "=f"(y) : "f"(x)); return y;
}

template <bool EXACT>
__device__ __forceinline__ float rnn_step(float h, float xv, float w_own,
                                          unsigned own_addr, unsigned vec_addr,
                                          const float w[8], float Bj, float wih) {
    asm volatile("st.shared.f32 [%0], %1;" :: "r"(own_addr), "f"(h) : "memory");
    float v0, v1, v2, v3, v4, v5, v6, v7;
    asm volatile("ld.shared.v4.f32 {%0,%1,%2,%3}, [%4];"
                 : "=f"(v0), "=f"(v1), "=f"(v2), "=f"(v3)
                 : "r"(vec_addr) : "memory");
    asm volatile("ld.shared.v4.f32 {%0,%1,%2,%3}, [%4];"
                 : "=f"(v4), "=f"(v5), "=f"(v6), "=f"(v7)
                 : "r"(vec_addr + 16u) : "memory");
    // base: x-term + bias + OWN contribution from the register copy of h —
    // all computable while the LDS is in flight (w[own lane] is zeroed).
    float base = fmaf(xv, wih, Bj);
    base = fmaf(h, w_own, base);
    // arrival-ordered tree: v0-v3 (first LDS) deep, v4-v7 (second LDS) shallow
    float a = fmaf(v0, w[0], base);
    a = fmaf(v1, w[1], a);
    float b = v2 * w[2];
    b = fmaf(v3, w[3], b);
    float cc = v4 * w[4];
    cc = fmaf(v5, w[5], cc);
    float d = v6 * w[6];
    d = fmaf(v7, w[7], d);
    float s = (a + b) + (cc + d);
    if (EXACT) {
        const float c2 = 2.8853900817779268f; // 2*log2(e)
        float e = ex2f(c2 * s);
        float r = rcpf(e + 1.0f);
        return fmaf(-2.0f, r, 1.0f); // tanh(s) = 1 - 2*sigmoid(-2s)
    } else {
        return tanhf_approx(s);
    }
}

__global__ void __launch_bounds__(TBLOCK)
SmallRNN_kernel(const float* __restrict__ x,
                const float* __restrict__ w_ih,
                const float* __restrict__ w_hh,
                const float* __restrict__ b_ih,
                const float* __restrict__ b_hh,
                const float* __restrict__ fc_w,
                const float* __restrict__ fc_b,
                float* __restrict__ out,
                int B, int T) {
    __shared__ float sh[TBLOCK];

    int tx = threadIdx.x;
    int gtid = blockIdx.x * TBLOCK + tx;
    int b_raw = gtid >> 3;     // batch element
    int j = gtid & 7;          // hidden unit owned by this lane
    int b = (b_raw < B) ? b_raw : (B - 1);  // keep lanes active

    unsigned own_addr = (unsigned)__cvta_generic_to_shared(sh + tx);
    unsigned vec_addr = (unsigned)__cvta_generic_to_shared(sh + (tx & ~7));

    float w[8];
#pragma unroll
    for (int k = 0; k < 8; k++) w[k] = w_hh[j * 8 + k];
    float w_own = w[j];        // own contribution via register copy of h
    w[j] = 0.0f;               // zeroed in the tree (v[j]*0)
    float Bj  = b_ih[j] + b_hh[j];
    float wih = w_ih[j];

    const float* xp = x + (size_t)b * (size_t)T;
    float h = 0.0f; // h0 = 0

    int Tmain = T - EXACT_TAIL;
    if (Tmain < 0) Tmain = 0;
    int Tm = Tmain & ~15;

    if (((unsigned long long)xp & 15ull) == 0ull && Tm > 0) {
        float4 xa = *(const float4*)(xp);
        float4 xb_ = *(const float4*)(xp + 4);
        float4 xc = *(const float4*)(xp + 8);
        float4 xd = *(const float4*)(xp + 12);
        for (int t = 0; t < Tm; t += 16) {
            float4 n0, n1, n2, n3;
            if (t + 16 < Tm) {
                n0 = *(const float4*)(xp + t + 16);
                n1 = *(const float4*)(xp + t + 20);
                n2 = *(const float4*)(xp + t + 24);
                n3 = *(const float4*)(xp + t + 28);
            } else {
                n0 = make_float4(0.f, 0.f, 0.f, 0.f);
                n1 = n0; n2 = n0; n3 = n0;
            }
            h = rnn_step<false>(h, xa.x,  w_own, own_addr, vec_addr, w, Bj, wih);
            h = rnn_step<false>(h, xa.y,  w_own, own_addr, vec_addr, w, Bj, wih);
            h = rnn_step<false>(h, xa.z,  w_own, own_addr, vec_addr, w, Bj, wih);
            h = rnn_step<false>(h, xa.w,  w_own, own_addr, vec_addr, w, Bj, wih);
            h = rnn_step<false>(h, xb_.x, w_own, own_addr, vec_addr, w, Bj, wih);
            h = rnn_step<false>(h, xb_.y, w_own, own_addr, vec_addr, w, Bj, wih);
            h = rnn_step<false>(h, xb_.z, w_own, own_addr, vec_addr, w, Bj, wih);
            h = rnn_step<false>(h, xb_.w, w_own, own_addr, vec_addr, w, Bj, wih);
            h = rnn_step<false>(h, xc.x,  w_own, own_addr, vec_addr, w, Bj, wih);
            h = rnn_step<false>(h, xc.y,  w_own, own_addr, vec_addr, w, Bj, wih);
            h = rnn_step<false>(h, xc.z,  w_own, own_addr, vec_addr, w, Bj, wih);
            h = rnn_step<false>(h, xc.w,  w_own, own_addr, vec_addr, w, Bj, wih);
            h = rnn_step<false>(h, xd.x,  w_own, own_addr, vec_addr, w, Bj, wih);
            h = rnn_step<false>(h, xd.y,  w_own, own_addr, vec_addr, w, Bj, wih);
            h = rnn_step<false>(h, xd.z,  w_own, own_addr, vec_addr, w, Bj, wih);
            h = rnn_step<false>(h, xd.w,  w_own, own_addr, vec_addr, w, Bj, wih);
            xa = n0; xb_ = n1; xc = n2; xd = n3;
        }
    } else {
        Tm = 0;
    }
    for (int t = Tm; t < Tmain; t++) {
        h = rnn_step<false>(h, xp[t], w_own, own_addr, vec_addr, w, Bj, wih);
    }
    for (int t = Tmain; t < T; t++) {
        h = rnn_step<true>(h, xp[t], w_own, own_addr, vec_addr, w, Bj, wih);
    }

    // out[b] = sum_j h_j * fc_w[j] + fc_b
    float v = h * fc_w[j];
    v += __shfl_xor_sync(0xffffffffu, v, 4, 8);
    v += __shfl_xor_sync(0xffffffffu, v, 2, 8);
    v += __shfl_xor_sync(0xffffffffu, v, 1, 8);
    if (j == 0 && b_raw < B) out[b] = v + fc_b[0];
}

extern "C" void kernel_launch(void* const* d_in, const int* in_sizes, int n_in,
                              void* d_out, int out_size) {
    const float* x    = (const float*)d_in[0];
    const float* w_ih = (const float*)d_in[1];
    const float* w_hh = (const float*)d_in[2];
    const float* b_ih = (const float*)d_in[3];
    const float* b_hh = (const float*)d_in[4];
    const float* fc_w = (const float*)d_in[5];
    const float* fc_b = (const float*)d_in[6];
    float* out = (float*)d_out;

    int B = out_size;                 // O = 1
    int T = in_sizes[0] / B;          // I = 1
    int threads = B * 8;
    int grid = (threads + TBLOCK - 1) / TBLOCK;
    SmallRNN_kernel<<<grid, TBLOCK>>>(x, w_ih, w_hh, b_ih, b_hh, fc_w, fc_b,
                                      out, B, T);
}

// round 14
// speedup vs baseline: 1.3975x; 1.2632x over previous
#include <cuda_runtime.h>

// SmallRNN: h_t = tanh(x_t * w_ih^T + b_ih + h_{t-1} * w_hh^T + b_hh), out = h_T @ fc_w^T + fc_b
// Shapes: x [B=4096, T=2048, I=1], w_ih [8,1], w_hh [8,8], b_* [8], fc_w [1,8], fc_b [1]
//
// FINAL (= R6, best measured: 90.6us, rel_err 1.76e-7):
// 8 lanes per batch element (lane j owns h_j) — keeps chain MUFU count at 1.
// Exchange via shared memory: asm-pinned STS.32 -> 2x LDS.128 (broadcast,
// conflict-free); memory clobbers required (R4 showed the compiler reorders
// without them; R7 showed removing them regresses the schedule).
// Activation: tanh.approx.f32 for the first T-64 steps; exact ex2+rcp tanh for
// the last 64 steps. The recurrence contracts, so approx error from early
// steps is suppressed below fp32 rounding by the exact tail (verified: final
// rel_err identical to the all-exact version).
// Five structural/scheduling variants (shuffle exchange, lane repacking,
// element pairing, phase offset, unroll/peel changes) all measured slower:
// this is the dependency-chain floor of the algorithm on sm_103a.

#define TBLOCK 256
#define EXACT_TAIL 64

__device__ __forceinline__ float ex2f(float x) {
    float y; asm("ex2.approx.f32 %0, %1;" : "=f"(y) : "f"(x)); return y;
}
__device__ __forceinline__ float rcpf(float x) {
    float y; asm("rcp.approx.f32 %0, %1;" : "=f"(y) : "f"(x)); return y;
}
__device__ __forceinline__ float tanhf_approx(float x) {
    float y; asm("tanh.approx.f32 %0, %1;" : "=f"(y) : "f"(x)); return y;
}

template <bool EXACT>
__device__ __forceinline__ float rnn_step(float h, float xv,
                                          unsigned own_addr, unsigned vec_addr,
                                          const float w[8], float Bj, float wih) {
    // publish own h, then fetch the group's 8 values; asm volatile + memory
    // clobber pins ST->LD ordering (per-warp in-order smem LSU does the rest).
    asm volatile("st.shared.f32 [%0], %1;" :: "r"(own_addr), "f"(h) : "memory");
    float v0, v1, v2, v3, v4, v5, v6, v7;
    asm volatile("ld.shared.v4.f32 {%0,%1,%2,%3}, [%4];"
                 : "=f"(v0), "=f"(v1), "=f"(v2), "=f"(v3)
                 : "r"(vec_addr) : "memory");
    asm volatile("ld.shared.v4.f32 {%0,%1,%2,%3}, [%4];"
                 : "=f"(v4), "=f"(v5), "=f"(v6), "=f"(v7)
                 : "r"(vec_addr + 16u) : "memory");
    // 4-way split FMA tree, then combine; x-term and bias are off-chain
    float a = fmaf(xv, wih, Bj);
    a = fmaf(v0, w[0], a);
    float b = v1 * w[1];
    float cc = v2 * w[2];
    float d = v3 * w[3];
    a  = fmaf(v4, w[4], a);
    b  = fmaf(v5, w[5], b);
    cc = fmaf(v6, w[6], cc);
    d  = fmaf(v7, w[7], d);
    float s = (a + b) + (cc + d);
    if (EXACT) {
        const float c2 = 2.8853900817779268f; // 2*log2(e)
        float e = ex2f(c2 * s);
        float r = rcpf(e + 1.0f);
        return fmaf(-2.0f, r, 1.0f); // tanh(s) = 1 - 2*sigmoid(-2s)
    } else {
        return tanhf_approx(s);
    }
}

template <bool EXACT>
__device__ __forceinline__ float run_range(float h, const float* __restrict__ xp,
                                           int t0, int t1,
                                           unsigned own_addr, unsigned vec_addr,
                                           const float w[8], float Bj, float wih) {
    int span = t1 - t0;
    int Tm = span & ~7;
    const float* p = xp + t0;
    if (((unsigned long long)p & 15ull) == 0ull && Tm > 0) {
        float4 xa = *(const float4*)(p);
        float4 xb_ = *(const float4*)(p + 4);
        for (int t = 0; t < Tm; t += 8) {
            float4 xn0, xn1;
            if (t + 8 < Tm) {
                xn0 = *(const float4*)(p + t + 8);
                xn1 = *(const float4*)(p + t + 12);
            } else {
                xn0 = make_float4(0.f, 0.f, 0.f, 0.f);
                xn1 = xn0;
            }
            h = rnn_step<EXACT>(h, xa.x,  own_addr, vec_addr, w, Bj, wih);
            h = rnn_step<EXACT>(h, xa.y,  own_addr, vec_addr, w, Bj, wih);
            h = rnn_step<EXACT>(h, xa.z,  own_addr, vec_addr, w, Bj, wih);
            h = rnn_step<EXACT>(h, xa.w,  own_addr, vec_addr, w, Bj, wih);
            h = rnn_step<EXACT>(h, xb_.x, own_addr, vec_addr, w, Bj, wih);
            h = rnn_step<EXACT>(h, xb_.y, own_addr, vec_addr, w, Bj, wih);
            h = rnn_step<EXACT>(h, xb_.z, own_addr, vec_addr, w, Bj, wih);
            h = rnn_step<EXACT>(h, xb_.w, own_addr, vec_addr, w, Bj, wih);
            xa  = xn0;
            xb_ = xn1;
        }
    } else {
        Tm = 0;
    }
    for (int t = t0 + Tm; t < t1; t++) {
        h = rnn_step<EXACT>(h, xp[t], own_addr, vec_addr, w, Bj, wih);
    }
    return h;
}

__global__ void __launch_bounds__(TBLOCK)
SmallRNN_kernel(const float* __restrict__ x,
                const float* __restrict__ w_ih,
                const float* __restrict__ w_hh,
                const float* __restrict__ b_ih,
                const float* __restrict__ b_hh,
                const float* __restrict__ fc_w,
                const float* __restrict__ fc_b,
                float* __restrict__ out,
                int B, int T) {
    __shared__ float sh[TBLOCK];

    int tx = threadIdx.x;
    int gtid = blockIdx.x * TBLOCK + tx;
    int b_raw = gtid >> 3;     // batch element
    int j = gtid & 7;          // hidden unit owned by this lane
    int b = (b_raw < B) ? b_raw : (B - 1);  // keep lanes active

    unsigned own_addr = (unsigned)__cvta_generic_to_shared(sh + tx);
    unsigned vec_addr = (unsigned)__cvta_generic_to_shared(sh + (tx & ~7));

    float w[8];
#pragma unroll
    for (int k = 0; k < 8; k++) w[k] = w_hh[j * 8 + k];
    float Bj  = b_ih[j] + b_hh[j];
    float wih = w_ih[j];

    const float* xp = x + (size_t)b * (size_t)T;
    float h = 0.0f; // h0 = 0

    int Tmain = T - EXACT_TAIL;
    if (Tmain < 0) Tmain = 0;

    h = run_range<false>(h, xp, 0, Tmain, own_addr, vec_addr, w, Bj, wih);
    h = run_range<true >(h, xp, Tmain, T, own_addr, vec_addr, w, Bj, wih);

    // out[b] = sum_j h_j * fc_w[j] + fc_b
    float v = h * fc_w[j];
    v += __shfl_xor_sync(0xffffffffu, v, 4, 8);
    v += __shfl_xor_sync(0xffffffffu, v, 2, 8);
    v += __shfl_xor_sync(0xffffffffu, v, 1, 8);
    if (j == 0 && b_raw < B) out[b] = v + fc_b[0];
}

extern "C" void kernel_launch(void* const* d_in, const int* in_sizes, int n_in,
                              void* d_out, int out_size) {
    const float* x    = (const float*)d_in[0];
    const float* w_ih = (const float*)d_in[1];
    const float* w_hh = (const float*)d_in[2];
    const float* b_ih = (const float*)d_in[3];
    const float* b_hh = (const float*)d_in[4];
    const float* fc_w = (const float*)d_in[5];
    const float* fc_b = (const float*)d_in[6];
    float* out = (float*)d_out;

    int B = out_size;                 // O = 1
    int T = in_sizes[0] / B;          // I = 1
    int threads = B * 8;
    int grid = (threads + TBLOCK - 1) / TBLOCK;
    SmallRNN_kernel<<<grid, TBLOCK>>>(x, w_ih, w_hh, b_ih, b_hh, fc_w, fc_b,
                                      out, B, T);
}